// round 16
// baseline (speedup 1.0000x reference)
#include <cuda_runtime.h>

#define NB   16384
#define NJ   12
#define NQ   7
#define NO   5
#define NH1  128
#define NH2  128
#define GS   8
#define NBLOCKS (NB / GS)

#define W1_SZ (NQ * (NO + 1) * NH1)     // 5376
#define W2_SZ ((NH1 + 1) * NH2)         // 16512 floats per judge
#define W2Q_F4 ((NH1 + 1) * 32)         // float4 stride per judge (4128)
#define VT_ROW 132                      // [bias, w_1..w_128, 0,0,0]
#define VT_SZ (NQ * NO * VT_ROW)        // 4620
#define ZSTR 68                         // z1 row stride in floats ([k][sp0..3 x 16])
#define ZBUF_SZ (NH1 * ZSTR)            // 8704 >= 56*VT_ROW (7392)

// dynamic smem layout (floats)
#define OFF_ZBUF 0
#define OFF_SVT  (OFF_ZBUF + ZBUF_SZ)        // 8704
#define OFF_XS2  (OFF_SVT + VT_SZ)           // 13324
#define OFF_LG   (OFF_XS2 + NQ * NO * GS)    // 13604
#define OFF_IDX  (OFF_LG + GS * NQ * NO)     // 13884 (+16 ints)
#define SMEM_FLOATS (OFF_IDX + 20)
#define SMEM_BYTES  (SMEM_FLOATS * 4)

#define PREP_BLOCKS 64
#define PREP_THREADS 256

// ---------------- device scratch ----------------
__device__ int    g_mode64;
__device__ int    g_count[NJ];          // zero-initialized; re-zeroed by k_scan
__device__ int    g_cursor[NJ];
__device__ int    g_perm[NB];
__device__ float  g_cW1[NJ * W1_SZ];    // [j][q][i=0..5][h]
__device__ float4 g_cW2q[NJ * W2Q_F4];  // [j][i=0..128][lane l]: (w[l],w[l+32],w[l+64],w[l+96])
__device__ float  g_cVt[NJ * VT_SZ];    // [j][q][o][i=0..128,pad]

// ---------------- helpers ----------------
__device__ __forceinline__ float sigmoidf(float v) {
    return 1.0f / (1.0f + __expf(-v));
}
__device__ __forceinline__ unsigned long long pk(float a, float b) {
    unsigned long long r;
    asm("mov.b64 %0, {%1, %2};" : "=l"(r) : "f"(a), "f"(b));
    return r;
}
__device__ __forceinline__ void upk(unsigned long long v, float& lo, float& hi) {
    asm("mov.b64 {%0, %1}, %2;" : "=f"(lo), "=f"(hi) : "l"(v));
}
__device__ __forceinline__ void ffma2(unsigned long long& d,
                                      unsigned long long a,
                                      unsigned long long b) {
    asm("fma.rn.f32x2 %0, %1, %2, %0;" : "+l"(d) : "l"(a), "l"(b));
}

// ---------- detect judge-id dtype from the first 512 words ----------
__device__ __forceinline__ int detect_m64(const int* __restrict__ jw, int tid) {
    __shared__ int s_any;
    if (tid == 0) s_any = 0;
    __syncthreads();
    // int64 little-endian ids (0..11): every odd word is 0.
    if (jw[2 * (tid & 255) + 1] != 0) s_any = 1;   // benign race
    __syncthreads();
    return (s_any == 0);
}

// ================= prologue 1: histogram + dtype + weight combine =================
__global__ void __launch_bounds__(PREP_THREADS)
k_countw(const int* __restrict__ jw,
         const float* __restrict__ W1, const float* __restrict__ W1a,
         const float* __restrict__ W2, const float* __restrict__ W2a,
         const float* __restrict__ V,  const float* __restrict__ Va) {
    __shared__ int s_cnt[NJ];
    const int tid = threadIdx.x;
    const int b = blockIdx.x * PREP_THREADS + tid;

    const int m64 = detect_m64(jw, tid);
    if (blockIdx.x == 0 && tid == 0) g_mode64 = m64;

    if (tid < NJ) s_cnt[tid] = 0;
    __syncthreads();
    const int j = m64 ? jw[2 * b] : jw[b];
    atomicAdd(&s_cnt[j], 1);
    __syncthreads();
    if (tid < NJ && s_cnt[tid]) atomicAdd(&g_count[tid], s_cnt[tid]);

    const int n1 = NJ * W1_SZ;
    const int n2 = NJ * W2_SZ;
    const int n3 = NJ * VT_SZ;
    const int total = n1 + n2 + n3;
    float* w2q = (float*)g_cW2q;
    for (int i = blockIdx.x * PREP_THREADS + tid; i < total;
         i += PREP_BLOCKS * PREP_THREADS) {
        if (i < n1) {
            g_cW1[i] = W1[i % W1_SZ] + W1a[i];
        } else if (i < n1 + n2) {
            int r  = i - n1;                  // flat float idx into g_cW2q
            int jj = r / W2_SZ;
            int rem = r % W2_SZ;
            int ii = rem / 128;               // 0 = bias row, 1..128
            int c  = rem % 128;               // = lane*4 + comp
            int l  = c >> 2, comp = c & 3;
            int h  = comp * 32 + l;
            w2q[r] = W2[ii * 128 + h] + W2a[jj * W2_SZ + ii * 128 + h];
        } else {
            int r = i - n1 - n2;
            int ii = r % VT_ROW;              // 0 = bias, 1..128 = weights
            int rr = r / VT_ROW;              // ((j*NQ+q)*NO+o)
            int o  = rr % NO;
            int qq = (rr / NO) % NQ;
            int jj = rr / (NO * NQ);
            float v = 0.0f;
            if (ii <= NH2)
                v = V[(qq * (NH2 + 1) + ii) * NO + o] +
                    Va[((jj * NQ + qq) * (NH2 + 1) + ii) * NO + o];
            g_cVt[r] = v;
        }
    }
}

// ================= prologue 2: scan + reset =================
__global__ void k_scan() {
    if (threadIdx.x == 0) {
        int acc = 0;
        #pragma unroll
        for (int k = 0; k < NJ; k++) {
            g_cursor[k] = acc;
            acc += g_count[k];
            g_count[k] = 0;
        }
    }
}

// ================= prologue 3: scatter =================
__global__ void __launch_bounds__(PREP_THREADS)
k_scatter(const int* __restrict__ jw) {
    const int tid = threadIdx.x;
    const int b = blockIdx.x * PREP_THREADS + tid;
    const int j = g_mode64 ? jw[2 * b] : jw[b];
    int pos = atomicAdd(&g_cursor[j], 1);
    g_perm[pos] = b;
}

// ================= templated MLP body (UNI = all 8 samples same judge) =================
template <bool UNI>
__device__ __forceinline__ void mlp_body(
    int tid, const int* __restrict__ sj, const int* __restrict__ sb,
    const float* __restrict__ xs2, float* __restrict__ zbuf,
    const float* __restrict__ sVt, float* __restrict__ lg,
    float* __restrict__ out) {

    const int j0 = sj[0];
    const float* b1_0 = g_cW1 + j0 * W1_SZ;
    const float* b1p[GS];
    #pragma unroll
    for (int s = 0; s < GS; s++)
        b1p[s] = UNI ? b1_0 : g_cW1 + sj[s] * W1_SZ;

    // ---------- layer 1: thread = z1 row k; q in PAIRS; all 8 samples ----------
    // row layout per sp chunk (16 floats): q0sA,q0sB,q1sA,q1sB, ... ,q6sA,q6sB,0,0
    {
        float* row = zbuf + tid * ZSTR;
        #pragma unroll
        for (int qp = 0; qp < 4; qp++) {
            const int nqp = (qp == 3) ? 1 : 2;
            float a[2][GS];
            #pragma unroll
            for (int c = 0; c < 2; c++) {
                if (c >= nqp) {
                    #pragma unroll
                    for (int s = 0; s < GS; s++) a[c][s] = 0.f;
                    continue;
                }
                const int q = 2 * qp + c;
                int off = (q * (NO + 1)) * NH1 + tid;
                if (UNI) {
                    float w0 = b1_0[off];
                    #pragma unroll
                    for (int s = 0; s < GS; s++) a[c][s] = w0;
                } else {
                    #pragma unroll
                    for (int s = 0; s < GS; s++) a[c][s] = b1p[s][off];
                }
                #pragma unroll
                for (int i = 1; i <= NO; i++) {
                    off = (q * (NO + 1) + i) * NH1 + tid;
                    const float* xv = xs2 + (q * NO + i - 1) * GS;
                    float4 u = *(const float4*)(xv);
                    float4 v = *(const float4*)(xv + 4);
                    if (UNI) {
                        float w0 = b1_0[off];
                        a[c][0] = fmaf(u.x, w0, a[c][0]);
                        a[c][1] = fmaf(u.y, w0, a[c][1]);
                        a[c][2] = fmaf(u.z, w0, a[c][2]);
                        a[c][3] = fmaf(u.w, w0, a[c][3]);
                        a[c][4] = fmaf(v.x, w0, a[c][4]);
                        a[c][5] = fmaf(v.y, w0, a[c][5]);
                        a[c][6] = fmaf(v.z, w0, a[c][6]);
                        a[c][7] = fmaf(v.w, w0, a[c][7]);
                    } else {
                        a[c][0] = fmaf(u.x, b1p[0][off], a[c][0]);
                        a[c][1] = fmaf(u.y, b1p[1][off], a[c][1]);
                        a[c][2] = fmaf(u.z, b1p[2][off], a[c][2]);
                        a[c][3] = fmaf(u.w, b1p[3][off], a[c][3]);
                        a[c][4] = fmaf(v.x, b1p[4][off], a[c][4]);
                        a[c][5] = fmaf(v.y, b1p[5][off], a[c][5]);
                        a[c][6] = fmaf(v.z, b1p[6][off], a[c][6]);
                        a[c][7] = fmaf(v.w, b1p[7][off], a[c][7]);
                    }
                }
            }
            #pragma unroll
            for (int sp = 0; sp < 4; sp++) {
                float4 st = make_float4(sigmoidf(a[0][2 * sp]), sigmoidf(a[0][2 * sp + 1]),
                                        sigmoidf(a[1][2 * sp]), sigmoidf(a[1][2 * sp + 1]));
                *(float4*)(row + sp * 16 + qp * 4) = st;   // pads at 14,15 never read
            }
        }
    }
    __syncthreads();

    // ---------- layer 2: warp = sample-pair sp; lane owns h-quad (ln, +32, +64, +96)
    const int ln = tid & 31;
    const int sp = tid >> 5;                  // 0..3
    const int sA = 2 * sp, sB = sA + 1;

    const float4* wqA = g_cW2q + (size_t)(UNI ? j0 : sj[sA]) * W2Q_F4 + ln;
    const float4* wqB = UNI ? wqA : g_cW2q + (size_t)sj[sB] * W2Q_F4 + ln;

    unsigned long long acc[NQ][4];
    {   // bias row i = 0
        float4 wa = wqA[0];
        unsigned long long m0, m1, m2, m3;
        if (UNI) {
            m0 = pk(wa.x, wa.x); m1 = pk(wa.y, wa.y);
            m2 = pk(wa.z, wa.z); m3 = pk(wa.w, wa.w);
        } else {
            float4 wb = wqB[0];
            m0 = pk(wa.x, wb.x); m1 = pk(wa.y, wb.y);
            m2 = pk(wa.z, wb.z); m3 = pk(wa.w, wb.w);
        }
        #pragma unroll
        for (int q = 0; q < NQ; q++) {
            acc[q][0] = m0; acc[q][1] = m1; acc[q][2] = m2; acc[q][3] = m3;
        }
    }
    #pragma unroll 2
    for (int i = 1; i <= NH1; i++) {
        float4 wa = wqA[i * 32];
        unsigned long long m0, m1, m2, m3;
        if (UNI) {
            m0 = pk(wa.x, wa.x); m1 = pk(wa.y, wa.y);
            m2 = pk(wa.z, wa.z); m3 = pk(wa.w, wa.w);
        } else {
            float4 wb = wqB[i * 32];
            m0 = pk(wa.x, wb.x); m1 = pk(wa.y, wb.y);
            m2 = pk(wa.z, wb.z); m3 = pk(wa.w, wb.w);
        }
        const float* zb = zbuf + (i - 1) * ZSTR + sp * 16;
        ulonglong2 zA = *(const ulonglong2*)(zb);       // q0, q1 pairs
        ulonglong2 zB = *(const ulonglong2*)(zb + 4);   // q2, q3
        ulonglong2 zC = *(const ulonglong2*)(zb + 8);   // q4, q5
        unsigned long long zD = *(const unsigned long long*)(zb + 12);  // q6
        ffma2(acc[0][0], zA.x, m0); ffma2(acc[0][1], zA.x, m1);
        ffma2(acc[0][2], zA.x, m2); ffma2(acc[0][3], zA.x, m3);
        ffma2(acc[1][0], zA.y, m0); ffma2(acc[1][1], zA.y, m1);
        ffma2(acc[1][2], zA.y, m2); ffma2(acc[1][3], zA.y, m3);
        ffma2(acc[2][0], zB.x, m0); ffma2(acc[2][1], zB.x, m1);
        ffma2(acc[2][2], zB.x, m2); ffma2(acc[2][3], zB.x, m3);
        ffma2(acc[3][0], zB.y, m0); ffma2(acc[3][1], zB.y, m1);
        ffma2(acc[3][2], zB.y, m2); ffma2(acc[3][3], zB.y, m3);
        ffma2(acc[4][0], zC.x, m0); ffma2(acc[4][1], zC.x, m1);
        ffma2(acc[4][2], zC.x, m2); ffma2(acc[4][3], zC.x, m3);
        ffma2(acc[5][0], zC.y, m0); ffma2(acc[5][1], zC.y, m1);
        ffma2(acc[5][2], zC.y, m2); ffma2(acc[5][3], zC.y, m3);
        ffma2(acc[6][0], zD,   m0); ffma2(acc[6][1], zD,   m1);
        ffma2(acc[6][2], zD,   m2); ffma2(acc[6][3], zD,   m3);
    }
    __syncthreads();   // all z1 reads done before z2 overlays zbuf

    {   // sigmoid -> z2 rows [s*NQ+q][bias, h...]
        #pragma unroll
        for (int q = 0; q < NQ; q++) {
            #pragma unroll
            for (int c = 0; c < 4; c++) {
                const int h = c * 32 + ln;
                float eA, eB;
                upk(acc[q][c], eA, eB);
                zbuf[(sA * NQ + q) * VT_ROW + 1 + h] = sigmoidf(eA);
                zbuf[(sB * NQ + q) * VT_ROW + 1 + h] = sigmoidf(eB);
            }
        }
    }
    if (tid < GS * NQ) {                 // bias + zero pads
        float* row = zbuf + tid * VT_ROW;
        row[0] = 1.0f; row[129] = 0.0f; row[130] = 0.0f; row[131] = 0.0f;
    }
    if (UNI) asm volatile("cp.async.wait_group 0;" ::: "memory");
    __syncthreads();

    // ---------- layer 3: logits ----------
    for (int t = tid; t < GS * NQ * NO; t += 128) {
        int s = t / (NQ * NO), r = t % (NQ * NO), q = r / NO, o = r % NO;
        const ulonglong2* vz = (const ulonglong2*)(zbuf + (s * NQ + q) * VT_ROW);
        const ulonglong2* vv = UNI
            ? (const ulonglong2*)(sVt + (q * NO + o) * VT_ROW)
            : (const ulonglong2*)(g_cVt + (sj[s] * NQ * NO + q * NO + o) * VT_ROW);
        unsigned long long s0 = 0ULL, s1 = 0ULL;
        #pragma unroll 4
        for (int k = 0; k < VT_ROW / 4; k++) {
            ulonglong2 a = vz[k], bb = vv[k];
            ffma2(s0, a.x, bb.x);
            ffma2(s1, a.y, bb.y);
        }
        float f0, f1, f2, f3;
        upk(s0, f0, f1);
        upk(s1, f2, f3);
        lg[(s * NQ + q) * NO + o] = (f0 + f1) + (f2 + f3);
    }
    __syncthreads();

    // ---------- softmax + store ----------
    if (tid < GS * NQ) {
        int s = tid / NQ, q = tid % NQ;
        const float* lr = lg + tid * NO;
        float m = lr[0];
        #pragma unroll
        for (int o = 1; o < NO; o++) m = fmaxf(m, lr[o]);
        float e[NO], sum = 0.f;
        #pragma unroll
        for (int o = 0; o < NO; o++) { e[o] = __expf(lr[o] - m); sum += e[o]; }
        float inv = 1.0f / sum;
        float* op = out + (sb[s] * NQ + q) * NO;
        #pragma unroll
        for (int o = 0; o < NO; o++) op[o] = e[o] * inv;
    }
}

// ================= fused MLP, GS same-judge samples per block =================
__global__ void __launch_bounds__(128)
k_main(const float* __restrict__ x, const int* __restrict__ jw,
       float* __restrict__ out) {
    extern __shared__ __align__(16) float smem[];
    float* zbuf = smem + OFF_ZBUF;
    float* sVt  = smem + OFF_SVT;
    float* xs2  = smem + OFF_XS2;
    float* lg   = smem + OFF_LG;
    int*   sj   = (int*)(smem + OFF_IDX);
    int*   sb   = sj + GS;

    const int tid = threadIdx.x;

    if (tid < GS) {
        int b = g_perm[blockIdx.x * GS + tid];
        sb[tid] = b;
        sj[tid] = g_mode64 ? jw[2 * b] : jw[b];
    }
    __syncthreads();

    bool uni = true;
    #pragma unroll
    for (int s = 1; s < GS; s++) uni &= (sj[s] == sj[0]);

    // async prefetch of this judge's V^T (consumed only in layer 3)
    if (uni) {
        unsigned sdst = (unsigned)__cvta_generic_to_shared(sVt);
        unsigned long long gsrc;
        const float* p = g_cVt + sj[0] * VT_SZ;
        asm("cvta.to.global.u64 %0, %1;" : "=l"(gsrc) : "l"(p));
        for (int t = tid; t < VT_SZ / 4; t += 128)
            asm volatile("cp.async.ca.shared.global [%0], [%1], 16;"
                         :: "r"(sdst + t * 16), "l"(gsrc + (unsigned long long)t * 16));
        asm volatile("cp.async.commit_group;");
    }

    // stage x transposed: xs2[(q*5+o)*GS + s]
    for (int t = tid; t < GS * NQ * NO; t += 128) {
        int s = t / (NQ * NO), r = t % (NQ * NO);
        xs2[r * GS + s] = x[sb[s] * (NQ * NO) + r];
    }
    __syncthreads();

    if (uni) mlp_body<true >(tid, sj, sb, xs2, zbuf, sVt, lg, out);
    else     mlp_body<false>(tid, sj, sb, xs2, zbuf, sVt, lg, out);
}

// ---------------- launch ----------------
extern "C" void kernel_launch(void* const* d_in, const int* in_sizes, int n_in,
                              void* d_out, int out_size) {
    const float* x   = (const float*)d_in[0];
    const int*   jw  = (const int*)  d_in[1];
    const float* W1  = (const float*)d_in[2];
    const float* W1a = (const float*)d_in[3];
    const float* W2  = (const float*)d_in[4];
    const float* W2a = (const float*)d_in[5];
    const float* V   = (const float*)d_in[6];
    const float* Va  = (const float*)d_in[7];
    float* out = (float*)d_out;

    static bool attr_set = false;
    if (!attr_set) {
        cudaFuncSetAttribute(k_main, cudaFuncAttributeMaxDynamicSharedMemorySize,
                             SMEM_BYTES);
        attr_set = true;
    }

    k_countw <<<PREP_BLOCKS, PREP_THREADS>>>(jw, W1, W1a, W2, W2a, V, Va);
    k_scan   <<<1, 32>>>();
    k_scatter<<<PREP_BLOCKS, PREP_THREADS>>>(jw);
    k_main   <<<NBLOCKS, 128, SMEM_BYTES>>>(x, jw, out);
}

// round 17
// speedup vs baseline: 1.0680x; 1.0680x over previous
#include <cuda_runtime.h>

#define NB   16384
#define NJ   12
#define NQ   7
#define NO   5
#define NH1  128
#define NH2  128
#define GS   8
#define NBLOCKS (NB / GS)

#define W1_SZ (NQ * (NO + 1) * NH1)     // 5376
#define W2_SZ ((NH1 + 1) * NH2)         // 16512 floats per judge
#define W2Q_F4 ((NH1 + 1) * 32)         // float4 stride per judge (4128)
#define VT_ROW 132                      // [bias, w_1..w_128, 0,0,0]
#define VT_SZ (NQ * NO * VT_ROW)        // 4620
#define ZSTR 68                         // z1 row stride in floats ([k][sp0..3 x 16])
#define ZBUF_SZ (NH1 * ZSTR)            // 8704 >= 56*VT_ROW (7392)

#define PREP_BLOCKS 64
#define PREP_THREADS 256

// ---------------- device scratch ----------------
__device__ int    g_mode64;
__device__ int    g_count[NJ];          // zero-initialized; re-zeroed by k_scan
__device__ int    g_cursor[NJ];
__device__ int    g_perm[NB];
__device__ float  g_cW1[NJ * W1_SZ];    // [j][q][i=0..5][h]
__device__ float4 g_cW2q[NJ * W2Q_F4];  // [j][i=0..128][lane l]: (w[l],w[l+32],w[l+64],w[l+96])
__device__ float  g_cVt[NJ * VT_SZ];    // [j][q][o][i=0..128,pad]

// ---------------- helpers ----------------
__device__ __forceinline__ float sigmoidf(float v) {
    return 1.0f / (1.0f + __expf(-v));
}
__device__ __forceinline__ unsigned long long pk(float a, float b) {
    unsigned long long r;
    asm("mov.b64 %0, {%1, %2};" : "=l"(r) : "f"(a), "f"(b));
    return r;
}
__device__ __forceinline__ void upk(unsigned long long v, float& lo, float& hi) {
    asm("mov.b64 {%0, %1}, %2;" : "=f"(lo), "=f"(hi) : "l"(v));
}
__device__ __forceinline__ void ffma2(unsigned long long& d,
                                      unsigned long long a,
                                      unsigned long long b) {
    asm("fma.rn.f32x2 %0, %1, %2, %0;" : "+l"(d) : "l"(a), "l"(b));
}

// ---------- detect judge-id dtype from the first 512 words ----------
__device__ __forceinline__ int detect_m64(const int* __restrict__ jw, int tid) {
    __shared__ int s_any;
    if (tid == 0) s_any = 0;
    __syncthreads();
    // int64 little-endian ids (0..11): every odd word is 0.
    if (jw[2 * (tid & 255) + 1] != 0) s_any = 1;   // benign race
    __syncthreads();
    return (s_any == 0);
}

// ================= prologue 1: histogram + dtype + weight combine =================
__global__ void __launch_bounds__(PREP_THREADS)
k_countw(const int* __restrict__ jw,
         const float* __restrict__ W1, const float* __restrict__ W1a,
         const float* __restrict__ W2, const float* __restrict__ W2a,
         const float* __restrict__ V,  const float* __restrict__ Va) {
    __shared__ int s_cnt[NJ];
    const int tid = threadIdx.x;
    const int b = blockIdx.x * PREP_THREADS + tid;

    const int m64 = detect_m64(jw, tid);
    if (blockIdx.x == 0 && tid == 0) g_mode64 = m64;

    if (tid < NJ) s_cnt[tid] = 0;
    __syncthreads();
    const int j = m64 ? jw[2 * b] : jw[b];
    atomicAdd(&s_cnt[j], 1);
    __syncthreads();
    if (tid < NJ && s_cnt[tid]) atomicAdd(&g_count[tid], s_cnt[tid]);

    const int n1 = NJ * W1_SZ;
    const int n2 = NJ * W2_SZ;
    const int n3 = NJ * VT_SZ;
    const int total = n1 + n2 + n3;
    float* w2q = (float*)g_cW2q;
    for (int i = blockIdx.x * PREP_THREADS + tid; i < total;
         i += PREP_BLOCKS * PREP_THREADS) {
        if (i < n1) {
            g_cW1[i] = W1[i % W1_SZ] + W1a[i];
        } else if (i < n1 + n2) {
            int r  = i - n1;                  // flat float idx into g_cW2q
            int jj = r / W2_SZ;
            int rem = r % W2_SZ;
            int ii = rem / 128;               // 0 = bias row, 1..128
            int c  = rem % 128;               // = lane*4 + comp
            int l  = c >> 2, comp = c & 3;
            int h  = comp * 32 + l;
            w2q[r] = W2[ii * 128 + h] + W2a[jj * W2_SZ + ii * 128 + h];
        } else {
            int r = i - n1 - n2;
            int ii = r % VT_ROW;              // 0 = bias, 1..128 = weights
            int rr = r / VT_ROW;              // ((j*NQ+q)*NO+o)
            int o  = rr % NO;
            int qq = (rr / NO) % NQ;
            int jj = rr / (NO * NQ);
            float v = 0.0f;
            if (ii <= NH2)
                v = V[(qq * (NH2 + 1) + ii) * NO + o] +
                    Va[((jj * NQ + qq) * (NH2 + 1) + ii) * NO + o];
            g_cVt[r] = v;
        }
    }
}

// ================= prologue 2: scan + reset =================
__global__ void k_scan() {
    if (threadIdx.x == 0) {
        int acc = 0;
        #pragma unroll
        for (int k = 0; k < NJ; k++) {
            g_cursor[k] = acc;
            acc += g_count[k];
            g_count[k] = 0;
        }
    }
}

// ================= prologue 3: scatter =================
__global__ void __launch_bounds__(PREP_THREADS)
k_scatter(const int* __restrict__ jw) {
    const int tid = threadIdx.x;
    const int b = blockIdx.x * PREP_THREADS + tid;
    const int j = g_mode64 ? jw[2 * b] : jw[b];
    int pos = atomicAdd(&g_cursor[j], 1);
    g_perm[pos] = b;
}

// ================= templated MLP body (UNI = all 8 samples same judge) =================
template <bool UNI>
__device__ __forceinline__ void mlp_body(
    int tid, const int* __restrict__ sj, const int* __restrict__ sb,
    const float* __restrict__ xs2, float* __restrict__ zbuf,
    float* __restrict__ lg, float* __restrict__ out) {

    const int j0 = sj[0];
    const float* b1_0 = g_cW1 + j0 * W1_SZ;
    const float* b1p[GS];
    #pragma unroll
    for (int s = 0; s < GS; s++)
        b1p[s] = UNI ? b1_0 : g_cW1 + sj[s] * W1_SZ;

    // ---------- layer 1: thread = z1 row k; q in PAIRS; all 8 samples ----------
    // row layout per sp chunk (16 floats): q0sA,q0sB,q1sA,q1sB, ... ,q6sA,q6sB,0,0
    {
        float* row = zbuf + tid * ZSTR;
        #pragma unroll
        for (int qp = 0; qp < 4; qp++) {
            const int nqp = (qp == 3) ? 1 : 2;
            float a[2][GS];
            #pragma unroll
            for (int c = 0; c < 2; c++) {
                if (c >= nqp) {
                    #pragma unroll
                    for (int s = 0; s < GS; s++) a[c][s] = 0.f;
                    continue;
                }
                const int q = 2 * qp + c;
                int off = (q * (NO + 1)) * NH1 + tid;
                if (UNI) {
                    float w0 = b1_0[off];
                    #pragma unroll
                    for (int s = 0; s < GS; s++) a[c][s] = w0;
                } else {
                    #pragma unroll
                    for (int s = 0; s < GS; s++) a[c][s] = b1p[s][off];
                }
                #pragma unroll
                for (int i = 1; i <= NO; i++) {
                    off = (q * (NO + 1) + i) * NH1 + tid;
                    const float* xv = xs2 + (q * NO + i - 1) * GS;
                    float4 u = *(const float4*)(xv);
                    float4 v = *(const float4*)(xv + 4);
                    if (UNI) {
                        float w0 = b1_0[off];
                        a[c][0] = fmaf(u.x, w0, a[c][0]);
                        a[c][1] = fmaf(u.y, w0, a[c][1]);
                        a[c][2] = fmaf(u.z, w0, a[c][2]);
                        a[c][3] = fmaf(u.w, w0, a[c][3]);
                        a[c][4] = fmaf(v.x, w0, a[c][4]);
                        a[c][5] = fmaf(v.y, w0, a[c][5]);
                        a[c][6] = fmaf(v.z, w0, a[c][6]);
                        a[c][7] = fmaf(v.w, w0, a[c][7]);
                    } else {
                        a[c][0] = fmaf(u.x, b1p[0][off], a[c][0]);
                        a[c][1] = fmaf(u.y, b1p[1][off], a[c][1]);
                        a[c][2] = fmaf(u.z, b1p[2][off], a[c][2]);
                        a[c][3] = fmaf(u.w, b1p[3][off], a[c][3]);
                        a[c][4] = fmaf(v.x, b1p[4][off], a[c][4]);
                        a[c][5] = fmaf(v.y, b1p[5][off], a[c][5]);
                        a[c][6] = fmaf(v.z, b1p[6][off], a[c][6]);
                        a[c][7] = fmaf(v.w, b1p[7][off], a[c][7]);
                    }
                }
            }
            #pragma unroll
            for (int sp = 0; sp < 4; sp++) {
                float4 st = make_float4(sigmoidf(a[0][2 * sp]), sigmoidf(a[0][2 * sp + 1]),
                                        sigmoidf(a[1][2 * sp]), sigmoidf(a[1][2 * sp + 1]));
                *(float4*)(row + sp * 16 + qp * 4) = st;   // pads at 14,15 never read
            }
        }
    }
    __syncthreads();

    // ---------- layer 2: warp = sample-pair sp; lane owns h-quad (ln, +32, +64, +96)
    const int ln = tid & 31;
    const int wrp = tid >> 5;
    const int sp = wrp;                       // 0..3
    const int sA = 2 * sp, sB = sA + 1;

    const float4* wqA = g_cW2q + (size_t)(UNI ? j0 : sj[sA]) * W2Q_F4 + ln;
    const float4* wqB = UNI ? wqA : g_cW2q + (size_t)sj[sB] * W2Q_F4 + ln;

    unsigned long long acc[NQ][4];
    {   // bias row i = 0
        float4 wa = wqA[0];
        unsigned long long m0, m1, m2, m3;
        if (UNI) {
            m0 = pk(wa.x, wa.x); m1 = pk(wa.y, wa.y);
            m2 = pk(wa.z, wa.z); m3 = pk(wa.w, wa.w);
        } else {
            float4 wb = wqB[0];
            m0 = pk(wa.x, wb.x); m1 = pk(wa.y, wb.y);
            m2 = pk(wa.z, wb.z); m3 = pk(wa.w, wb.w);
        }
        #pragma unroll
        for (int q = 0; q < NQ; q++) {
            acc[q][0] = m0; acc[q][1] = m1; acc[q][2] = m2; acc[q][3] = m3;
        }
    }
    #pragma unroll 2
    for (int i = 1; i <= NH1; i++) {
        float4 wa = wqA[i * 32];
        unsigned long long m0, m1, m2, m3;
        if (UNI) {
            m0 = pk(wa.x, wa.x); m1 = pk(wa.y, wa.y);
            m2 = pk(wa.z, wa.z); m3 = pk(wa.w, wa.w);
        } else {
            float4 wb = wqB[i * 32];
            m0 = pk(wa.x, wb.x); m1 = pk(wa.y, wb.y);
            m2 = pk(wa.z, wb.z); m3 = pk(wa.w, wb.w);
        }
        const float* zb = zbuf + (i - 1) * ZSTR + sp * 16;
        ulonglong2 zA = *(const ulonglong2*)(zb);       // q0, q1 pairs
        ulonglong2 zB = *(const ulonglong2*)(zb + 4);   // q2, q3
        ulonglong2 zC = *(const ulonglong2*)(zb + 8);   // q4, q5
        unsigned long long zD = *(const unsigned long long*)(zb + 12);  // q6
        ffma2(acc[0][0], zA.x, m0); ffma2(acc[0][1], zA.x, m1);
        ffma2(acc[0][2], zA.x, m2); ffma2(acc[0][3], zA.x, m3);
        ffma2(acc[1][0], zA.y, m0); ffma2(acc[1][1], zA.y, m1);
        ffma2(acc[1][2], zA.y, m2); ffma2(acc[1][3], zA.y, m3);
        ffma2(acc[2][0], zB.x, m0); ffma2(acc[2][1], zB.x, m1);
        ffma2(acc[2][2], zB.x, m2); ffma2(acc[2][3], zB.x, m3);
        ffma2(acc[3][0], zB.y, m0); ffma2(acc[3][1], zB.y, m1);
        ffma2(acc[3][2], zB.y, m2); ffma2(acc[3][3], zB.y, m3);
        ffma2(acc[4][0], zC.x, m0); ffma2(acc[4][1], zC.x, m1);
        ffma2(acc[4][2], zC.x, m2); ffma2(acc[4][3], zC.x, m3);
        ffma2(acc[5][0], zC.y, m0); ffma2(acc[5][1], zC.y, m1);
        ffma2(acc[5][2], zC.y, m2); ffma2(acc[5][3], zC.y, m3);
        ffma2(acc[6][0], zD,   m0); ffma2(acc[6][1], zD,   m1);
        ffma2(acc[6][2], zD,   m2); ffma2(acc[6][3], zD,   m3);
    }
    __syncthreads();   // all z1 reads done before z2 overlays zbuf

    {   // sigmoid -> z2 rows [s*NQ+q][bias, h...]
        #pragma unroll
        for (int q = 0; q < NQ; q++) {
            #pragma unroll
            for (int c = 0; c < 4; c++) {
                const int h = c * 32 + ln;
                float eA, eB;
                upk(acc[q][c], eA, eB);
                zbuf[(sA * NQ + q) * VT_ROW + 1 + h] = sigmoidf(eA);
                zbuf[(sB * NQ + q) * VT_ROW + 1 + h] = sigmoidf(eB);
            }
        }
    }
    if (tid < GS * NQ) {                 // bias + zero pads
        float* row = zbuf + tid * VT_ROW;
        row[0] = 1.0f; row[129] = 0.0f; row[130] = 0.0f; row[131] = 0.0f;
    }
    __syncthreads();

    // ---------- layer 3: warp-cooperative logits (56 tasks / 4 warps = 14 rounds)
    for (int r = 0; r < (GS * NQ) / 4; r++) {
        const int task = r * 4 + wrp;
        const int s = task / NQ, q = task - s * NQ;
        const float* zr = zbuf + task * VT_ROW;
        float za = zr[ln], zb2 = zr[ln + 32], zc = zr[ln + 64], zd = zr[ln + 96];
        float z128 = zr[128];
        const int jj = UNI ? j0 : sj[s];
        const float* vb = g_cVt + ((size_t)jj * NQ + q) * (NO * VT_ROW);
        #pragma unroll
        for (int o = 0; o < NO; o++) {
            const float* vr = vb + o * VT_ROW;
            float p = za * vr[ln];
            p = fmaf(zb2, vr[ln + 32], p);
            p = fmaf(zc,  vr[ln + 64], p);
            p = fmaf(zd,  vr[ln + 96], p);
            if (ln == 0) p = fmaf(z128, vr[128], p);
            p += __shfl_xor_sync(0xffffffffu, p, 16);
            p += __shfl_xor_sync(0xffffffffu, p, 8);
            p += __shfl_xor_sync(0xffffffffu, p, 4);
            p += __shfl_xor_sync(0xffffffffu, p, 2);
            p += __shfl_xor_sync(0xffffffffu, p, 1);
            if (ln == 0) lg[task * NO + o] = p;
        }
    }
    __syncthreads();

    // ---------- softmax + store ----------
    if (tid < GS * NQ) {
        int s = tid / NQ, q = tid % NQ;
        const float* lr = lg + tid * NO;
        float m = lr[0];
        #pragma unroll
        for (int o = 1; o < NO; o++) m = fmaxf(m, lr[o]);
        float e[NO], sum = 0.f;
        #pragma unroll
        for (int o = 0; o < NO; o++) { e[o] = __expf(lr[o] - m); sum += e[o]; }
        float inv = 1.0f / sum;
        float* op = out + (sb[s] * NQ + q) * NO;
        #pragma unroll
        for (int o = 0; o < NO; o++) op[o] = e[o] * inv;
    }
}

// ================= fused MLP, GS same-judge samples per block =================
__global__ void __launch_bounds__(128, 5)
k_main(const float* __restrict__ x, const int* __restrict__ jw,
       float* __restrict__ out) {
    __shared__ int   sb[GS], sj[GS];
    __shared__ __align__(16) float xs2[NQ * NO * GS];    // [q][o][s0..s7]
    // union: layer1 z1 [k][sp x 16] (8704 f)  then  z2 [56][VT_ROW] (7392 f)
    __shared__ __align__(16) float zbuf[ZBUF_SZ];
    __shared__ float lg[GS * NQ * NO];

    const int tid = threadIdx.x;

    if (tid < GS) {
        int b = g_perm[blockIdx.x * GS + tid];
        sb[tid] = b;
        sj[tid] = g_mode64 ? jw[2 * b] : jw[b];
    }
    __syncthreads();

    bool uni = true;
    #pragma unroll
    for (int s = 1; s < GS; s++) uni &= (sj[s] == sj[0]);

    // stage x transposed: xs2[(q*5+o)*GS + s]
    for (int t = tid; t < GS * NQ * NO; t += 128) {
        int s = t / (NQ * NO), r = t % (NQ * NO);
        xs2[r * GS + s] = x[sb[s] * (NQ * NO) + r];
    }
    __syncthreads();

    if (uni) mlp_body<true >(tid, sj, sb, xs2, zbuf, lg, out);
    else     mlp_body<false>(tid, sj, sb, xs2, zbuf, lg, out);
}

// ---------------- launch ----------------
extern "C" void kernel_launch(void* const* d_in, const int* in_sizes, int n_in,
                              void* d_out, int out_size) {
    const float* x   = (const float*)d_in[0];
    const int*   jw  = (const int*)  d_in[1];
    const float* W1  = (const float*)d_in[2];
    const float* W1a = (const float*)d_in[3];
    const float* W2  = (const float*)d_in[4];
    const float* W2a = (const float*)d_in[5];
    const float* V   = (const float*)d_in[6];
    const float* Va  = (const float*)d_in[7];
    float* out = (float*)d_out;

    k_countw <<<PREP_BLOCKS, PREP_THREADS>>>(jw, W1, W1a, W2, W2a, V, Va);
    k_scan   <<<1, 32>>>();
    k_scatter<<<PREP_BLOCKS, PREP_THREADS>>>(jw);
    k_main   <<<NBLOCKS, 128>>>(x, jw, out);
}